// round 3
// baseline (speedup 1.0000x reference)
#include <cuda_runtime.h>

// DisplacementMap (tfa dense_image_warp, bilinear) — B=8, H=512, W=512, C=16, fp32.
// R3: 8 lanes per pixel. One LDG.128 warp-request covers the full 128-byte
// top span (tl||tr, both pixels' 16 channels) and one covers the bottom span,
// so L1 wavefronts carry full lines instead of 64B halves. Lanes exchange
// halves via shfl_xor(4); upper half-group computes with alpha -> 1-alpha
// (same FMA form), only lanes sub<4 store (warp stores remain fully dense).

#define H_DIM 512
#define W_DIM 512
#define C_DIM 16
#define B_DIM 8

__global__ __launch_bounds__(256) void displacement_map_kernel(
    const float* __restrict__ x,
    const float* __restrict__ flow,
    float* __restrict__ out)
{
    const int gid = blockIdx.x * blockDim.x + threadIdx.x;
    const int sub = gid & 7;     // lane within 8-lane pixel group
    const int pix = gid >> 3;    // linear pixel over B*H*W

    const int w = pix & (W_DIM - 1);
    const int h = (pix >> 9) & (H_DIM - 1);

    // flow: 8 lanes of a group hit the same 8 bytes -> single broadcast request.
    const float2 f = __ldcs(reinterpret_cast<const float2*>(flow) + pix);

    const float qy = (float)h - f.x;
    const float qx = (float)w - f.y;

    float fy = fminf(fmaxf(floorf(qy), 0.0f), (float)(H_DIM - 2));
    float fx = fminf(fmaxf(floorf(qx), 0.0f), (float)(W_DIM - 2));
    const float ay = fminf(fmaxf(qy - fy, 0.0f), 1.0f);
    const float ax = fminf(fmaxf(qx - fx, 0.0f), 1.0f);
    const int iy = (int)fy;
    const int ix = (int)fx;

    // Base of x[b, iy, ix, 0] in float4 units. 8 lanes * 16B = 128B span
    // covering channels of pixel ix (64B) then pixel ix+1 (64B).
    const size_t top4 =
        ((((size_t)(pix >> 18) * H_DIM + (size_t)iy) * W_DIM + (size_t)ix) * C_DIM) >> 2;
    const size_t bot4 = top4 + ((size_t)W_DIM * C_DIM / 4);  // +2048

    const float4* __restrict__ xf4 = reinterpret_cast<const float4*>(x);

    // Two front-batched 128B-span gathers.
    const float4 t = xf4[top4 + sub];
    const float4 b = xf4[bot4 + sub];

    // Exchange halves: lane sub gets lane sub^4's value.
    float4 ot, ob;
    ot.x = __shfl_xor_sync(0xFFFFFFFFu, t.x, 4);
    ot.y = __shfl_xor_sync(0xFFFFFFFFu, t.y, 4);
    ot.z = __shfl_xor_sync(0xFFFFFFFFu, t.z, 4);
    ot.w = __shfl_xor_sync(0xFFFFFFFFu, t.w, 4);
    ob.x = __shfl_xor_sync(0xFFFFFFFFu, b.x, 4);
    ob.y = __shfl_xor_sync(0xFFFFFFFFu, b.y, 4);
    ob.z = __shfl_xor_sync(0xFFFFFFFFu, b.z, 4);
    ob.w = __shfl_xor_sync(0xFFFFFFFFu, b.w, 4);

    // Lanes sub<4 hold tl in t, tr in ot  -> r = t + ax*(ot - t)
    // Lanes sub>=4 hold tr in t, tl in ot -> r = t + (1-ax)*(ot - t)  (same value)
    const float axe = (sub < 4) ? ax : (1.0f - ax);

    float4 r;
    {
        float tt, bb;
        tt = t.x + axe * (ot.x - t.x);  bb = b.x + axe * (ob.x - b.x);
        r.x = tt + ay * (bb - tt);
        tt = t.y + axe * (ot.y - t.y);  bb = b.y + axe * (ob.y - b.y);
        r.y = tt + ay * (bb - tt);
        tt = t.z + axe * (ot.z - t.z);  bb = b.z + axe * (ob.z - b.z);
        r.z = tt + ay * (bb - tt);
        tt = t.w + axe * (ot.w - t.w);  bb = b.w + axe * (ob.w - b.w);
        r.w = tt + ay * (bb - tt);
    }

    // Only the lower half-group stores (cg = sub). Warp's 16 active lanes
    // cover 4 pixels * 64B = 256B contiguous -> two fully-dense 128B lines.
    if (sub < 4) {
        __stcs(reinterpret_cast<float4*>(out) + ((size_t)pix * 4 + sub), r);
    }
}

extern "C" void kernel_launch(void* const* d_in, const int* in_sizes, int n_in,
                              void* d_out, int out_size)
{
    const float* x    = (const float*)d_in[0];
    const float* flow = (const float*)d_in[1];
    float* out        = (float*)d_out;

    // 8 lanes per pixel.
    const long long total = (long long)B_DIM * H_DIM * W_DIM * 8;  // 16,777,216
    const int block = 256;
    const int grid  = (int)(total / block);                        // 65536

    displacement_map_kernel<<<grid, block>>>(x, flow, out);
}

// round 4
// speedup vs baseline: 1.5294x; 1.5294x over previous
#include <cuda_runtime.h>

// DisplacementMap (tfa dense_image_warp, bilinear) — B=8, H=512, W=512, C=16, fp32.
// R4 = R1 (best: 57us, traffic-minimal) + dense sequential L2 prefetch of x.
// Rationale: DRAM traffic is already compulsory-minimum, but the gather
// presents DRAM with randomly-ordered 64B reads -> row-activate bound (~55%).
// Each CTA prefetches its own 4KB slice of x in linear order (union = whole
// tensor, once). L2 MSHRs merge the later demand gathers with the in-flight
// dense prefetch stream, so DRAM sees sequential traffic.

#define H_DIM 512
#define W_DIM 512
#define C_DIM 16
#define B_DIM 8

__global__ __launch_bounds__(256) void displacement_map_kernel(
    const float* __restrict__ x,
    const float* __restrict__ flow,
    float* __restrict__ out)
{
    const int gid = blockIdx.x * blockDim.x + threadIdx.x;
    const int cg  = gid & 3;          // channel group: 4 floats
    const int pix = gid >> 2;         // linear pixel index over B*H*W

    // ---- dense L2 prefetch of this CTA's own x slice ----
    // CTA covers 64 pixels -> 64 * 64B = 4KB = 32 lines of 128B.
    // Warp 0's 32 lanes each prefetch one line, in linear order.
    if (threadIdx.x < 32) {
        const size_t cta_byte0 = (size_t)blockIdx.x * 64 * 64;  // pix0 * 64B
        const char* p = reinterpret_cast<const char*>(x) + cta_byte0
                        + (size_t)threadIdx.x * 128;
        asm volatile("prefetch.global.L2 [%0];" :: "l"(p));
    }

    const int w = pix & (W_DIM - 1);
    const int h = (pix >> 9) & (H_DIM - 1);

    // flow: 4 lanes of a pixel read the same 8 bytes -> L1 broadcast.
    const float2 f = reinterpret_cast<const float2*>(flow)[pix];

    const float qy = (float)h - f.x;
    const float qx = (float)w - f.y;

    float fy = floorf(qy);
    float fx = floorf(qx);
    fy = fminf(fmaxf(fy, 0.0f), (float)(H_DIM - 2));
    fx = fminf(fmaxf(fx, 0.0f), (float)(W_DIM - 2));

    const float ay = fminf(fmaxf(qy - fy, 0.0f), 1.0f);
    const float ax = fminf(fmaxf(qx - fx, 0.0f), 1.0f);

    const int iy = (int)fy;
    const int ix = (int)fx;
    const int b_hw = pix >> 18;  // batch

    const size_t base_f4 =
        ((((size_t)b_hw * H_DIM + (size_t)iy) * W_DIM + (size_t)ix) * C_DIM) >> 2;

    const float4* __restrict__ xf4 = reinterpret_cast<const float4*>(x);
    const size_t row_stride_f4 = (size_t)W_DIM * C_DIM / 4;  // 2048

    // Four independent gathers (MLP=4).
    const float4 tl = xf4[base_f4 + cg];
    const float4 tr = xf4[base_f4 + cg + (C_DIM / 4)];
    const float4 bl = xf4[base_f4 + cg + row_stride_f4];
    const float4 br = xf4[base_f4 + cg + row_stride_f4 + (C_DIM / 4)];

    float4 r;
    {
        const float tx0 = tl.x + ax * (tr.x - tl.x);
        const float tx1 = tl.y + ax * (tr.y - tl.y);
        const float tx2 = tl.z + ax * (tr.z - tl.z);
        const float tx3 = tl.w + ax * (tr.w - tl.w);
        const float bx0 = bl.x + ax * (br.x - bl.x);
        const float bx1 = bl.y + ax * (br.y - bl.y);
        const float bx2 = bl.z + ax * (br.z - bl.z);
        const float bx3 = bl.w + ax * (br.w - bl.w);
        r.x = tx0 + ay * (bx0 - tx0);
        r.y = tx1 + ay * (bx1 - tx1);
        r.z = tx2 + ay * (bx2 - tx2);
        r.w = tx3 + ay * (bx3 - tx3);
    }

    reinterpret_cast<float4*>(out)[gid] = r;
}

extern "C" void kernel_launch(void* const* d_in, const int* in_sizes, int n_in,
                              void* d_out, int out_size)
{
    const float* x    = (const float*)d_in[0];
    const float* flow = (const float*)d_in[1];
    float* out        = (float*)d_out;

    // total threads = B*H*W*4 (4 channel-groups per pixel)
    const int total = B_DIM * H_DIM * W_DIM * 4;  // 8,388,608
    const int block = 256;
    const int grid  = total / block;              // 32768

    displacement_map_kernel<<<grid, block>>>(x, flow, out);
}